// round 16
// baseline (speedup 1.0000x reference)
#include <cuda_runtime.h>
#include <cstdint>

// Problem constants (fixed by setup_inputs)
#define B_ 16
#define T_ 8192
#define D_ 64
#define D2 (D_ / 2)       // 32 float2 columns
#define CHUNK 16          // == WINDOW
#define CPT 4             // chunks per thread -> 64 timesteps per thread
#define TPT (CHUNK * CPT) // 64
#define YDIM 4
#define BLOCK_T (TPT * YDIM) // 256 timesteps per block

__device__ __forceinline__ float fexp2(float x) {
    float y; asm("ex2.approx.ftz.f32 %0, %1;" : "=f"(y) : "f"(x)); return y;
}
__device__ __forceinline__ float flog2(float x) {
    float y; asm("lg2.approx.ftz.f32 %0, %1;" : "=f"(y) : "f"(x)); return y;
}
__device__ __forceinline__ void cp_async8(uint32_t saddr, const void* gptr) {
    asm volatile("cp.async.ca.shared.global [%0], [%1], 8;" :: "r"(saddr), "l"(gptr));
}
__device__ __forceinline__ void cp_commit() {
    asm volatile("cp.async.commit_group;");
}
template <int N>
__device__ __forceinline__ void cp_wait() {
    asm volatile("cp.async.wait_group %0;" :: "n"(N));
}

// out[b,t,d] = -(1/5) * log( sum_{k=0..15} exp(-5 * x[b, max(t-k,0), d]) )
// Chunked prefix/suffix decomposition, streaming stores, in-place suffix.
// R16: cp.async (LDGSTS) double-buffered prefetch — chunk c+1's loads fly
// global->smem WITHOUT registers while chunk c computes. This hides the
// chunk-boundary L2 round-trip (the ~22% residual stall) at ~45 live regs,
// evading the RF wall that killed register-resident prefetch (R7/R12).
// Per-thread wait_group ordering: each thread consumes only its own smem
// slots, so no __syncthreads is needed anywhere.
__global__ __launch_bounds__(128) void always_kernel(
    const float* __restrict__ lower,
    const float* __restrict__ upper,
    float* __restrict__ out)
{
    // [parity][y][r][lane] -> 2*4*16*32*8 = 32 KB
    __shared__ float2 sbuf[2][YDIM][CHUNK][D2];

    const float C1 = -7.2134752044448169f;   // -5 * log2(e)
    const float C2 = -0.13862943611198906f;  // -ln(2) / 5

    const int d2 = threadIdx.x;              // 0..31 float2 column (coalesced)
    const int ty = threadIdx.y;              // 0..3
    const int b  = blockIdx.y;               // 0..15
    const int tr = blockIdx.z;               // 0: lower, 1: upper
    const int t0 = blockIdx.x * BLOCK_T + ty * TPT;

    const float* src = tr ? upper : lower;
    float*       dst = out + (size_t)tr * ((size_t)B_ * T_ * D_);

    const float2* col  = (const float2*)src + (size_t)b * T_ * D2 + d2;
    float2*       ocol = (float2*)dst      + (size_t)b * T_ * D2 + d2;

    uint32_t sb0 = (uint32_t)__cvta_generic_to_shared(&sbuf[0][ty][0][d2]);
    uint32_t sb1 = (uint32_t)__cvta_generic_to_shared(&sbuf[1][ty][0][d2]);
    const int RSTRIDE = D2 * (int)sizeof(float2);   // 256 bytes between r slots

    // Prefetch chunk 0 into buffer 0 (in flight during halo processing).
    #pragma unroll
    for (int r = 0; r < 16; r++)
        cp_async8(sb0 + r * RSTRIDE, col + (t0 + r) * D2);
    cp_commit();

    // Halo suffix sums of the 15 preceding (index-clamped) timesteps via
    // plain LDG (they feed ex2 immediately). Clamp to 0 reproduces h0's
    // replication of x[:,0,:] exactly (duplicates ARE counted in the
    // logsumexp, matching the reference).
    float sfx[16], sfy[16];                  // slots 1..15 used
    {
        float2 vh[16];
        #pragma unroll
        for (int k = 1; k < 16; k++) {
            int t = t0 - 16 + k;
            if (t < 0) t = 0;
            vh[k] = col[t * D2];
        }
        #pragma unroll
        for (int k = 1; k < 16; k++) {
            sfx[k] = fexp2(vh[k].x * C1);
            sfy[k] = fexp2(vh[k].y * C1);
        }
        #pragma unroll
        for (int k = 14; k >= 1; k--) { sfx[k] += sfx[k + 1]; sfy[k] += sfy[k + 1]; }
    }

    #pragma unroll 1
    for (int c = 0; c < CPT; c++) {
        const int tc = t0 + c * CHUNK;

        // Issue next chunk's prefetch BEFORE waiting on this chunk, keeping
        // the LDGSTS queue busy; then wait until this chunk's group landed.
        if (c + 1 < CPT) {
            uint32_t sbn = ((c + 1) & 1) ? sb1 : sb0;
            #pragma unroll
            for (int r = 0; r < 16; r++)
                cp_async8(sbn + r * RSTRIDE, col + (tc + CHUNK + r) * D2);
            cp_commit();
            cp_wait<1>();                    // this chunk's group complete
        } else {
            cp_wait<0>();                    // last chunk: drain everything
        }

        const float2* vbuf = &sbuf[c & 1][ty][0][d2];

        // Fused pass: window_sum = prefix_cur[r] + suffix_prev[r+1].
        // e[r] is written into sf[r] IN PLACE: sf[r] was last read at step
        // r-1, so the slot is dead by the time step r overwrites it.
        float px = 0.0f, py = 0.0f;
        #pragma unroll
        for (int r = 0; r < 16; r++) {
            float2 v = vbuf[r * D2];         // LDS.64, conflict-free
            float ex = fexp2(v.x * C1);
            float ey = fexp2(v.y * C1);
            px += ex;
            py += ey;
            float wx = (r < 15) ? (px + sfx[r + 1]) : px;
            float wy = (r < 15) ? (py + sfy[r + 1]) : py;
            float2 o;
            o.x = flog2(wx) * C2;
            o.y = flog2(wy) * C2;
            __stcs(&ocol[(tc + r) * D2], o); // evict-first: outputs never re-read
            if (r >= 1) { sfx[r] = ex; sfy[r] = ey; }  // e[0] never needed again
        }

        // Reverse-accumulate in place -> suffix sums for the next chunk.
        if (c + 1 < CPT) {
            #pragma unroll
            for (int k = 14; k >= 1; k--) { sfx[k] += sfx[k + 1]; sfy[k] += sfy[k + 1]; }
        }
    }
}

extern "C" void kernel_launch(void* const* d_in, const int* in_sizes, int n_in,
                              void* d_out, int out_size) {
    const float* lower = (const float*)d_in[0];
    const float* upper = (const float*)d_in[1];
    float* out = (float*)d_out;

    dim3 block(D2, YDIM);                  // 32 x 4 = 128 threads
    dim3 grid(T_ / BLOCK_T, B_, 2);        // 32 x 16 x 2 = 1024 blocks
    always_kernel<<<grid, block>>>(lower, upper, out);
}

// round 17
// speedup vs baseline: 1.2414x; 1.2414x over previous
#include <cuda_runtime.h>

// Problem constants (fixed by setup_inputs)
#define B_ 16
#define T_ 8192
#define D_ 64
#define D2 (D_ / 2)       // 32 float2 columns
#define CHUNK 16          // == WINDOW
#define CPT 2             // chunks per thread -> 32 timesteps per thread
#define TPT (CHUNK * CPT) // 32
#define YDIM 4
#define BLOCK_T (TPT * YDIM) // 128 timesteps per block

__device__ __forceinline__ float fexp2(float x) {
    float y; asm("ex2.approx.ftz.f32 %0, %1;" : "=f"(y) : "f"(x)); return y;
}
__device__ __forceinline__ float flog2(float x) {
    float y; asm("lg2.approx.ftz.f32 %0, %1;" : "=f"(y) : "f"(x)); return y;
}

// out[b,t,d] = -(1/5) * log( sum_{k=0..15} exp(-5 * x[b, max(t-k,0), d]) )
// FINAL — R13 config, session best (20.54us harness / 19.39us ncu; 1.7x
// over the first working version). 16-round search summary:
// - Chunked prefix/suffix decomposition: window [t-15,t] spans <=2 aligned
//   16-chunks; window_sum = prefix_cur[r] + suffix_prev[r+1]. Fully
//   parallel, numerically exact vs the reference scan (rel_err 7e-8).
//   Index clamp to 0 reproduces h0's replication of x[:,0,:] exactly.
// - float2 over D: LDG.64/STG.64 coalesced. float4 loses (reg blowup,
//   R12); float1 loses (LSU issue floor, R2).
// - __stcs streaming stores: measured win (R6) — outputs never re-read.
// - In-place suffix construction: live set fits 64 regs (R8).
// - 2048 x 128-thread blocks, CPT=2: ~27-32 resident warps x 16-deep MLP
//   is the measured optimum. More warps at shallower MLP loses (R14);
//   fewer warps at deeper MLP loses (R7/R9/R12); cp.async smem prefetch
//   loses (R16); forced pipelining loses (R5/R10).
__global__ __launch_bounds__(128, 8) void always_kernel(
    const float* __restrict__ lower,
    const float* __restrict__ upper,
    float* __restrict__ out)
{
    const float C1 = -7.2134752044448169f;   // -5 * log2(e)
    const float C2 = -0.13862943611198906f;  // -ln(2) / 5

    const int d2 = threadIdx.x;              // 0..31 float2 column (coalesced)
    const int b  = blockIdx.y;               // 0..15
    const int tr = blockIdx.z;               // 0: lower, 1: upper
    const int t0 = blockIdx.x * BLOCK_T + threadIdx.y * TPT;

    const float* src = tr ? upper : lower;
    float*       dst = out + (size_t)tr * ((size_t)B_ * T_ * D_);

    const float2* col  = (const float2*)src + (size_t)b * T_ * D2 + d2;
    float2*       ocol = (float2*)dst      + (size_t)b * T_ * D2 + d2;

    // Halo suffix sums of the 15 preceding (index-clamped) timesteps.
    float sfx[16], sfy[16];                  // slots 1..15 used
    {
        float2 vh[16];
        #pragma unroll
        for (int k = 1; k < 16; k++) {
            int t = t0 - 16 + k;
            if (t < 0) t = 0;
            vh[k] = col[t * D2];
        }
        #pragma unroll
        for (int k = 1; k < 16; k++) {
            sfx[k] = fexp2(vh[k].x * C1);
            sfy[k] = fexp2(vh[k].y * C1);
        }
        #pragma unroll
        for (int k = 14; k >= 1; k--) { sfx[k] += sfx[k + 1]; sfy[k] += sfy[k + 1]; }
    }

    #pragma unroll 1
    for (int c = 0; c < CPT; c++) {
        const int tc = t0 + c * CHUNK;

        // 16 independent LDG.64 -> 16-deep MLP per warp (measured optimum).
        float2 v[16];
        #pragma unroll
        for (int r = 0; r < 16; r++) v[r] = col[(tc + r) * D2];

        // Fused pass: window_sum = prefix_cur[r] + suffix_prev[r+1].
        // e[r] overwrites sf[r] IN PLACE (sf[r] dead after step r-1).
        float px = 0.0f, py = 0.0f;
        #pragma unroll
        for (int r = 0; r < 16; r++) {
            float ex = fexp2(v[r].x * C1);
            float ey = fexp2(v[r].y * C1);
            px += ex;
            py += ey;
            float wx = (r < 15) ? (px + sfx[r + 1]) : px;
            float wy = (r < 15) ? (py + sfy[r + 1]) : py;
            float2 o;
            o.x = flog2(wx) * C2;
            o.y = flog2(wy) * C2;
            __stcs(&ocol[(tc + r) * D2], o);   // evict-first: outputs never re-read
            if (r >= 1) { sfx[r] = ex; sfy[r] = ey; }  // e[0] never needed again
        }

        // Reverse-accumulate in place -> suffix sums for the next chunk.
        if (c + 1 < CPT) {
            #pragma unroll
            for (int k = 14; k >= 1; k--) { sfx[k] += sfx[k + 1]; sfy[k] += sfy[k + 1]; }
        }
    }
}

extern "C" void kernel_launch(void* const* d_in, const int* in_sizes, int n_in,
                              void* d_out, int out_size) {
    const float* lower = (const float*)d_in[0];
    const float* upper = (const float*)d_in[1];
    float* out = (float*)d_out;

    dim3 block(D2, YDIM);                  // 32 x 4 = 128 threads
    dim3 grid(T_ / BLOCK_T, B_, 2);        // 64 x 16 x 2 = 2048 blocks
    always_kernel<<<grid, block>>>(lower, upper, out);
}